// round 10
// baseline (speedup 1.0000x reference)
#include <cuda_runtime.h>

// ReLU_Conv (CROWN-style ReLU relaxation over bound maps)
// Round 10: 1 neuron per 64-thread block -> MLP=8 front-batched streaming
//           LDG.128 per thread at 16 blocks/SM (32 warps, 64-reg budget).
//           Probes the untested (MLP=8, medium-residency) corner between
//           R3 (MLP8/24w -> 79.1% DRAM) and R6 (MLP4/48w -> 80.1% DRAM).
//           2-warp combine via one cheap barrier, redundant finalize,
//           streaming cache hints.
// Output layout: [lx_out | ux_out | lc_out | uc_out]

__device__ __forceinline__ void acc_pair(const float4 l, const float4 u,
                                         const float4 mn, const float4 mx,
                                         float& sl, float& su)
{
    // (l>0 ? mn : (l<0 ? mx : 0)) * l == (l>0 ? mn : mx) * l  (finite bounds)
    sl += (l.x > 0.f ? mn.x : mx.x) * l.x;
    su += (u.x > 0.f ? mx.x : mn.x) * u.x;
    sl += (l.y > 0.f ? mn.y : mx.y) * l.y;
    su += (u.y > 0.f ? mx.y : mn.y) * u.y;
    sl += (l.z > 0.f ? mn.z : mx.z) * l.z;
    su += (u.z > 0.f ? mx.z : mn.z) * u.z;
    sl += (l.w > 0.f ? mn.w : mx.w) * l.w;
    su += (u.w > 0.f ? mx.w : mn.w) * u.w;
}

__global__ __launch_bounds__(64, 16)
void relu_conv_kernel(
    const float* __restrict__ lx, const float* __restrict__ ux,
    const float* __restrict__ lc, const float* __restrict__ uc,
    const float* __restrict__ xmin, const float* __restrict__ xmax,
    float* __restrict__ lx_out, float* __restrict__ ux_out,
    float* __restrict__ lc_out, float* __restrict__ uc_out)
{
    const int tid = threadIdx.x;                       // 0..63
    const int n   = blockIdx.x;                        // this block's neuron
    const size_t base = (size_t)n * 1024;

    // Front-batched streaming loads: 8x LDG.128 per thread
    // (thread covers float4 slots tid + 64*i, i=0..3, for lx and ux).
    const float4* plx = reinterpret_cast<const float4*>(lx + base) + tid;
    const float4* pux = reinterpret_cast<const float4*>(ux + base) + tid;
    float4 vlx[4], vux[4];
    #pragma unroll
    for (int i = 0; i < 4; i++) vlx[i] = __ldcs(plx + i * 64);
    #pragma unroll
    for (int i = 0; i < 4; i++) vux[i] = __ldcs(pux + i * 64);
    const float lcv = __ldg(lc + n);
    const float ucv = __ldg(uc + n);

    // Broadcast bounds: 8 KB total, L1-resident after wave 1.
    float sl = 0.f, su = 0.f;
    #pragma unroll
    for (int i = 0; i < 4; i++) {
        const float4 mn = __ldg(reinterpret_cast<const float4*>(xmin) + tid + i * 64);
        const float4 mx = __ldg(reinterpret_cast<const float4*>(xmax) + tid + i * 64);
        acc_pair(vlx[i], vux[i], mn, mx, sl, su);
    }

    // Warp reduction.
    #pragma unroll
    for (int off = 16; off; off >>= 1) {
        sl += __shfl_down_sync(0xffffffffu, sl, off);
        su += __shfl_down_sync(0xffffffffu, su, off);
    }

    __shared__ float2 sPart[2];                        // per-warp partials
    const int warp = tid >> 5, lane = tid & 31;
    if (lane == 0) sPart[warp] = make_float2(sl, su);
    __syncthreads();                                   // 2-warp barrier (only one)

    // Every thread redundantly finalizes (broadcast smem reads).
    const float2 p0 = sPart[0], p1 = sPart[1];
    const float l = p0.x + p1.x + lcv;
    const float u = p0.y + p1.y + ucv;

    const bool alive = (l >= 0.f);
    const bool cross = (l < 0.f) && (u > 0.f);
    float slope = cross ? (u / (u - l)) : 1.f;
    slope = fminf(fmaxf(slope, 0.f), 1.f);

    if (tid == 0) {
        lc_out[n] = alive ? lcv : 0.f;
        uc_out[n] = alive ? ucv : (cross ? (slope * ucv - slope * l) : 0.f);
    }

    float4* qlx = reinterpret_cast<float4*>(lx_out + base) + tid;
    float4* qux = reinterpret_cast<float4*>(ux_out + base) + tid;
    #pragma unroll
    for (int i = 0; i < 4; i++) {
        float4 o;
        o.x = alive ? vlx[i].x : 0.f;
        o.y = alive ? vlx[i].y : 0.f;
        o.z = alive ? vlx[i].z : 0.f;
        o.w = alive ? vlx[i].w : 0.f;
        __stcs(qlx + i * 64, o);
    }
    #pragma unroll
    for (int i = 0; i < 4; i++) {
        float4 o;
        o.x = alive ? vux[i].x : (cross ? slope * vux[i].x : 0.f);
        o.y = alive ? vux[i].y : (cross ? slope * vux[i].y : 0.f);
        o.z = alive ? vux[i].z : (cross ? slope * vux[i].z : 0.f);
        o.w = alive ? vux[i].w : (cross ? slope * vux[i].w : 0.f);
        __stcs(qux + i * 64, o);
    }
}

extern "C" void kernel_launch(void* const* d_in, const int* in_sizes, int n_in,
                              void* d_out, int out_size)
{
    const float* lx   = (const float*)d_in[0];
    const float* ux   = (const float*)d_in[1];
    const float* lc   = (const float*)d_in[2];
    const float* uc   = (const float*)d_in[3];
    const float* xmin = (const float*)d_in[4];
    const float* xmax = (const float*)d_in[5];

    const int neurons = in_sizes[2];          // C*H*W = 32768
    const size_t nel  = (size_t)neurons * 1024;

    float* out    = (float*)d_out;
    float* lx_out = out;
    float* ux_out = out + nel;
    float* lc_out = out + 2 * nel;
    float* uc_out = out + 2 * nel + neurons;

    relu_conv_kernel<<<neurons, 64>>>(lx, ux, lc, uc, xmin, xmax,
                                      lx_out, ux_out, lc_out, uc_out);
}